// round 7
// baseline (speedup 1.0000x reference)
#include <cuda_runtime.h>
#include <math.h>
#include <stdint.h>

#define N_NODES 2048
#define IN_F    128
#define OUT_F   32
#define KC      256
#define NTILES  (N_NODES / KC)          // 8
#define NSTEP   (KC / 32)               // 8
#define LOG2E   1.4426950408889634f
#define ABS2    0x7fffffff7fffffffull
#define PBIAS   8.0f                    // p stored as 2^(e-8) in fp16

// Score kernel shape: 128 thr = 4 warps x 2 rows = 8 rows/CTA, grid 256
#define S_THREADS 128
#define S_STAGE_FLOATS (KC * OUT_F + KC)      // 8448
#define S_STAGE_BYTES  (S_STAGE_FLOATS * 4)   // 33792
#define S_SMEM_BYTES   (2 * S_STAGE_BYTES)    // 67584

// Agg kernel shape: 128 thr = 4 warps x 4 rows = 16 rows/CTA, grid 128
#define A_THREADS 128
#define A_STAGE_BYTES (KC * OUT_F * 4)        // 32768
#define A_SMEM_BYTES  (2 * A_STAGE_BYTES)     // 65536

__device__ float          g_Wh1[N_NODES * OUT_F];   // raw Wh1 (agg)
__device__ float          g_Wh2s[N_NODES * OUT_F];  // 0.4*log2e*a_f * Wh2 (score)
__device__ float          g_c6L[N_NODES];           // log2e*0.6*dot(a,Wh1[i]) - PBIAS
__device__ float          g_dk6L[N_NODES];          // log2e*0.6*dot(a,Wh2[k])
__device__ unsigned short g_P[N_NODES * N_NODES];   // fp16 p * 2^-8
__device__ float          g_L[N_NODES];             // row sums of p (biased)

// ---------------------------------------------------------------------------
// Kernel 1: projections + per-row constants
// ---------------------------------------------------------------------------
__global__ __launch_bounds__(256) void gat_gemm_kernel(
    const float* __restrict__ h, const float* __restrict__ W,
    const float* __restrict__ a)
{
    __shared__ float Ws[2 * IN_F * OUT_F];
    __shared__ float hs[16][IN_F];
    const int tx = threadIdx.x, ty = threadIdx.y;   // (32, 8)
    const int tid = ty * 32 + tx;
    const int row0 = blockIdx.x * 16;

    for (int i = tid; i < (2 * IN_F * OUT_F) / 4; i += 256)
        ((float4*)Ws)[i] = ((const float4*)W)[i];
    for (int i = tid; i < (16 * IN_F) / 4; i += 256)
        ((float4*)&hs[0][0])[i] = ((const float4*)(h + (size_t)row0 * IN_F))[i];
    __syncthreads();

    float w1A = 0.f, w2A = 0.f, w1B = 0.f, w2B = 0.f;
#pragma unroll 4
    for (int j = 0; j < IN_F; ++j) {
        const float s1 = Ws[j * OUT_F + tx];
        const float s2 = Ws[(IN_F + j) * OUT_F + tx];
        const float hA = hs[ty][j];
        const float hB = hs[ty + 8][j];
        w1A = fmaf(hA, s1, w1A);  w2A = fmaf(hA, s2, w2A);
        w1B = fmaf(hB, s1, w1B);  w2B = fmaf(hB, s2, w2B);
    }

    const int rowA = row0 + ty, rowB = row0 + ty + 8;
    const float av = a[tx];
    const float A = (0.4f * LOG2E) * av;
    g_Wh1[rowA * OUT_F + tx]  = w1A;  g_Wh2s[rowA * OUT_F + tx] = A * w2A;
    g_Wh1[rowB * OUT_F + tx]  = w1B;  g_Wh2s[rowB * OUT_F + tx] = A * w2B;

    float cA = av * w1A, dA = av * w2A, cB = av * w1B, dB = av * w2B;
#pragma unroll
    for (int off = 16; off; off >>= 1) {
        cA += __shfl_xor_sync(0xffffffffu, cA, off);
        dA += __shfl_xor_sync(0xffffffffu, dA, off);
        cB += __shfl_xor_sync(0xffffffffu, cB, off);
        dB += __shfl_xor_sync(0xffffffffu, dB, off);
    }
    if (tx == 0) {
        g_c6L[rowA]  = (0.6f * LOG2E) * cA - PBIAS;   // fold fp16 bias here
        g_dk6L[rowA] = (0.6f * LOG2E) * dA;
        g_c6L[rowB]  = (0.6f * LOG2E) * cB - PBIAS;
        g_dk6L[rowB] = (0.6f * LOG2E) * dB;
    }
}

// ---------------------------------------------------------------------------
// Kernel 2: scores -> masked p (fp16, biased) + row sums
// ---------------------------------------------------------------------------
extern __shared__ float smem2[];

__device__ __forceinline__ void issue_tile_score(int t, uint32_t smem_u, int tid)
{
    const uint32_t w2b = smem_u + (t & 1) * S_STAGE_BYTES;
    const uint32_t dkb = w2b + KC * OUT_F * 4;
    const float4* g2 = ((const float4*)g_Wh2s) + t * (KC * 8);
    for (int i = tid; i < KC * 8; i += S_THREADS) {
        int kk = i >> 3, f4 = i & 7;
        uint32_t soff = (uint32_t)(((kk << 3) | (f4 ^ (kk & 7))) << 4);
        asm volatile("cp.async.cg.shared.global [%0], [%1], 16;"
                     :: "r"(w2b + soff), "l"(g2 + i) : "memory");
    }
    const float* gd = g_dk6L + t * KC;
    for (int i = tid; i < KC; i += S_THREADS)
        asm volatile("cp.async.ca.shared.global [%0], [%1], 4;"
                     :: "r"(dkb + (uint32_t)(i * 4)), "l"(gd + i) : "memory");
    asm volatile("cp.async.commit_group;" ::: "memory");
}

__global__ __launch_bounds__(S_THREADS, 3) void gat_score_kernel(
    const int* __restrict__ adj, const float* __restrict__ a)
{
    const int tid = threadIdx.x, w = tid >> 5, lane = tid & 31;
    const uint32_t smem_u = (uint32_t)__cvta_generic_to_shared(smem2);
    const int row0 = blockIdx.x * 8 + 2 * w;     // grid 256 covers exactly 2048
    const int row1 = row0 + 1;

    unsigned long long swh1[2][16], sig[16];
#pragma unroll
    for (int j = 0; j < 16; ++j) {
        float a0 = __ldg(a + 2 * j), a1 = __ldg(a + 2 * j + 1);
        sig[j] = (unsigned long long)(__float_as_uint(a0) & 0x80000000u)
               | ((unsigned long long)(__float_as_uint(a1) & 0x80000000u) << 32);
        float A0 = (0.4f * LOG2E) * a0, A1 = (0.4f * LOG2E) * a1;
        float x0 = A0 * g_Wh1[row0 * OUT_F + 2 * j];
        float x1 = A1 * g_Wh1[row0 * OUT_F + 2 * j + 1];
        float y0 = A0 * g_Wh1[row1 * OUT_F + 2 * j];
        float y1 = A1 * g_Wh1[row1 * OUT_F + 2 * j + 1];
        asm("mov.b64 %0, {%1, %2};" : "=l"(swh1[0][j]) : "f"(x0), "f"(x1));
        asm("mov.b64 %0, {%1, %2};" : "=l"(swh1[1][j]) : "f"(y0), "f"(y1));
    }
    const float c0 = g_c6L[row0], c1 = g_c6L[row1];   // already -PBIAS
    float lsum0 = 0.f, lsum1 = 0.f;

    const int* adjr0 = adj + (size_t)row0 * N_NODES;
    const int* adjr1 = adj + (size_t)row1 * N_NODES;
    // Per-lane bases: this lane writes k = (t<<8) + (step<<5) + lane,
    // so the base includes +lane and the offset must NOT re-add it.
    unsigned short* p0base = g_P + (size_t)row0 * N_NODES + lane;
    unsigned short* p1base = g_P + (size_t)row1 * N_NODES + lane;

    int am0[NSTEP], am1[NSTEP];
#pragma unroll
    for (int s = 0; s < NSTEP; ++s) {
        am0[s] = __ldg(adjr0 + (s << 5) + lane);
        am1[s] = __ldg(adjr1 + (s << 5) + lane);
    }

    issue_tile_score(0, smem_u, tid);

#pragma unroll 1
    for (int t = 0; t < NTILES; ++t) {
        __syncthreads();
        if (t + 1 < NTILES) {
            issue_tile_score(t + 1, smem_u, tid);
            asm volatile("cp.async.wait_group 1;" ::: "memory");
        } else {
            asm volatile("cp.async.wait_group 0;" ::: "memory");
        }
        __syncthreads();

        const uint32_t w2b = smem_u + (t & 1) * S_STAGE_BYTES;
        const float* sdk = smem2 + (t & 1) * S_STAGE_FLOATS + KC * OUT_F;
        const int* nadj0 = adjr0 + (((t + 1) & (NTILES - 1)) << 8);
        const int* nadj1 = adjr1 + (((t + 1) & (NTILES - 1)) << 8);

#pragma unroll
        for (int step = 0; step < NSTEP; ++step) {
            const int kk = (step << 5) | lane;
            const int av0 = am0[step], av1 = am1[step];
            am0[step] = __ldg(nadj0 + (step << 5) + lane);
            am1[step] = __ldg(nadj1 + (step << 5) + lane);
            const float dkv = sdk[kk];
            const uint32_t rb2 = w2b + (uint32_t)(kk << 7);
            const int sx = kk & 7;

            unsigned long long s0a = 0ull, s0b = 0ull, s1a = 0ull, s1b = 0ull;
#pragma unroll
            for (int f4 = 0; f4 < 8; ++f4) {
                unsigned long long v0, v1, u;
                asm volatile("ld.shared.v2.b64 {%0, %1}, [%2];"
                             : "=l"(v0), "=l"(v1) : "r"(rb2 + (uint32_t)((f4 ^ sx) << 4)));
                const int j0 = 2 * f4, j1 = 2 * f4 + 1;
                asm("add.rn.f32x2 %0, %1, %2;" : "=l"(u) : "l"(swh1[0][j0]), "l"(v0));
                u = (u & ABS2) ^ sig[j0];               // single LOP3 per half
                asm("add.rn.f32x2 %0, %0, %1;" : "+l"(s0a) : "l"(u));
                asm("add.rn.f32x2 %0, %1, %2;" : "=l"(u) : "l"(swh1[0][j1]), "l"(v1));
                u = (u & ABS2) ^ sig[j1];
                asm("add.rn.f32x2 %0, %0, %1;" : "+l"(s0b) : "l"(u));
                asm("add.rn.f32x2 %0, %1, %2;" : "=l"(u) : "l"(swh1[1][j0]), "l"(v0));
                u = (u & ABS2) ^ sig[j0];
                asm("add.rn.f32x2 %0, %0, %1;" : "+l"(s1a) : "l"(u));
                asm("add.rn.f32x2 %0, %1, %2;" : "=l"(u) : "l"(swh1[1][j1]), "l"(v1));
                u = (u & ABS2) ^ sig[j1];
                asm("add.rn.f32x2 %0, %0, %1;" : "+l"(s1b) : "l"(u));
            }

            const int koff = (t << 8) + (step << 5);   // lane already in base
            {
                unsigned long long ts; float lo, hi, e, p, pu;
                unsigned short us;
                asm("add.rn.f32x2 %0, %1, %2;" : "=l"(ts) : "l"(s0a), "l"(s0b));
                asm("mov.b64 {%0, %1}, %2;" : "=f"(lo), "=f"(hi) : "l"(ts));
                e = (c0 + dkv) + (lo + hi);
                asm("ex2.approx.f32 %0, %1;" : "=f"(p) : "f"(e));
                p = (av0 > 0) ? p : 0.f;
                asm("cvt.rn.f16.f32 %0, %1;" : "=h"(us) : "f"(p));
                asm("cvt.f32.f16 %0, %1;" : "=f"(pu) : "h"(us));
                lsum0 += pu;                         // consistent with stored p
                p0base[koff] = us;                   // coalesced u16 store
                asm("add.rn.f32x2 %0, %1, %2;" : "=l"(ts) : "l"(s1a), "l"(s1b));
                asm("mov.b64 {%0, %1}, %2;" : "=f"(lo), "=f"(hi) : "l"(ts));
                e = (c1 + dkv) + (lo + hi);
                asm("ex2.approx.f32 %0, %1;" : "=f"(p) : "f"(e));
                p = (av1 > 0) ? p : 0.f;
                asm("cvt.rn.f16.f32 %0, %1;" : "=h"(us) : "f"(p));
                asm("cvt.f32.f16 %0, %1;" : "=f"(pu) : "h"(us));
                lsum1 += pu;
                p1base[koff] = us;
            }
        }
    }

#pragma unroll
    for (int o = 16; o; o >>= 1) {
        lsum0 += __shfl_xor_sync(0xffffffffu, lsum0, o);
        lsum1 += __shfl_xor_sync(0xffffffffu, lsum1, o);
    }
    if (lane == 0) { g_L[row0] = lsum0; g_L[row1] = lsum1; }
}

// ---------------------------------------------------------------------------
// Kernel 3: out = ELU( (P @ Wh1) / L ).  4 rows per lane.
// ---------------------------------------------------------------------------
__device__ __forceinline__ void issue_tile_agg(int t, uint32_t smem_u, int tid)
{
    const uint32_t w1b = smem_u + (t & 1) * A_STAGE_BYTES;
    const float4* g1 = ((const float4*)g_Wh1) + t * (KC * 8);
    for (int i = tid; i < KC * 8; i += A_THREADS) {
        int kk = i >> 3, f4 = i & 7;
        uint32_t soff = (uint32_t)(((kk << 3) | (f4 ^ (kk & 7))) << 4);
        asm volatile("cp.async.cg.shared.global [%0], [%1], 16;"
                     :: "r"(w1b + soff), "l"(g1 + i) : "memory");
    }
    asm volatile("cp.async.commit_group;" ::: "memory");
}

__global__ __launch_bounds__(A_THREADS, 2) void gat_agg_kernel(float* __restrict__ out)
{
    const int tid = threadIdx.x, w = tid >> 5, lane = tid & 31;
    const uint32_t smem_u = (uint32_t)__cvta_generic_to_shared(smem2);
    const int rowb = blockIdx.x * 16 + 4 * w;    // grid 128 covers exactly 2048

    unsigned long long acc[4][16];
#pragma unroll
    for (int r = 0; r < 4; ++r)
#pragma unroll
        for (int j = 0; j < 16; ++j) acc[r][j] = 0ull;

    const unsigned short* pB[4];
#pragma unroll
    for (int r = 0; r < 4; ++r) pB[r] = g_P + (size_t)(rowb + r) * N_NODES + lane;

    unsigned pr[4][NSTEP];
#pragma unroll
    for (int r = 0; r < 4; ++r)
#pragma unroll
        for (int s = 0; s < NSTEP; ++s) pr[r][s] = __ldg(pB[r] + (s << 5));

    issue_tile_agg(0, smem_u, tid);

#pragma unroll 1
    for (int t = 0; t < NTILES; ++t) {
        __syncthreads();
        if (t + 1 < NTILES) {
            issue_tile_agg(t + 1, smem_u, tid);
            asm volatile("cp.async.wait_group 1;" ::: "memory");
        } else {
            asm volatile("cp.async.wait_group 0;" ::: "memory");
        }
        __syncthreads();

        const uint32_t w1b = smem_u + (t & 1) * A_STAGE_BYTES;
        const int noff = ((t + 1) & (NTILES - 1)) << 8;

#pragma unroll
        for (int step = 0; step < NSTEP; ++step) {
            const int kk = (step << 5) | lane;
            unsigned long long p2[4];
#pragma unroll
            for (int r = 0; r < 4; ++r) {
                float pf;
                asm("cvt.f32.f16 %0, %1;" : "=f"(pf) : "h"((unsigned short)pr[r][step]));
                pr[r][step] = __ldg(pB[r] + noff + (step << 5));
                asm("mov.b64 %0, {%1, %1};" : "=l"(p2[r]) : "f"(pf));
            }
            const uint32_t rb1 = w1b + (uint32_t)(kk << 7);
            const int sx = kk & 7;
#pragma unroll
            for (int f4 = 0; f4 < 8; ++f4) {
                unsigned long long v0, v1;
                asm volatile("ld.shared.v2.b64 {%0, %1}, [%2];"
                             : "=l"(v0), "=l"(v1) : "r"(rb1 + (uint32_t)((f4 ^ sx) << 4)));
#pragma unroll
                for (int r = 0; r < 4; ++r) {
                    asm("fma.rn.f32x2 %0, %1, %2, %0;" : "+l"(acc[r][2*f4])   : "l"(p2[r]), "l"(v0));
                    asm("fma.rn.f32x2 %0, %1, %2, %0;" : "+l"(acc[r][2*f4+1]) : "l"(p2[r]), "l"(v1));
                }
            }
        }
    }

    // Epilogue: per-warp cross-lane transpose reduce (private smem region)
    __syncthreads();
    float* red = smem2 + w * (32 * 33);
#pragma unroll 1
    for (int r = 0; r < 4; ++r) {
#pragma unroll
        for (int j = 0; j < 16; ++j) {
            float lo, hi;
            asm("mov.b64 {%0, %1}, %2;" : "=f"(lo), "=f"(hi) : "l"(acc[r][j]));
            red[lane * 33 + 2 * j]     = lo;
            red[lane * 33 + 2 * j + 1] = hi;
        }
        __syncwarp();
        float tot = 0.f;
#pragma unroll 8
        for (int jj = 0; jj < 32; ++jj) tot += red[jj * 33 + lane];
        const int row = rowb + r;
        const float hv = tot / __ldg(g_L + row);
        out[row * OUT_F + lane] = hv > 0.f ? hv : expm1f(hv);
        __syncwarp();
    }
}

// ---------------------------------------------------------------------------
extern "C" void kernel_launch(void* const* d_in, const int* in_sizes, int n_in,
                              void* d_out, int out_size)
{
    const float* h   = (const float*)d_in[0];
    const int*   adj = (const int*)  d_in[1];
    const float* W   = (const float*)d_in[2];
    const float* a   = (const float*)d_in[3];
    float*       out = (float*)d_out;

    gat_gemm_kernel<<<N_NODES / 16, dim3(32, 8)>>>(h, W, a);

    cudaFuncSetAttribute(gat_score_kernel,
                         cudaFuncAttributeMaxDynamicSharedMemorySize, S_SMEM_BYTES);
    gat_score_kernel<<<256, S_THREADS, S_SMEM_BYTES>>>(adj, a);

    cudaFuncSetAttribute(gat_agg_kernel,
                         cudaFuncAttributeMaxDynamicSharedMemorySize, A_SMEM_BYTES);
    gat_agg_kernel<<<128, A_THREADS, A_SMEM_BYTES>>>(out);
}

// round 8
// speedup vs baseline: 1.0745x; 1.0745x over previous
#include <cuda_runtime.h>
#include <math.h>
#include <stdint.h>

#define N_NODES 2048
#define IN_F    128
#define OUT_F   32
#define KC      256
#define NSTEP   (KC / 32)               // 8
#define KSPLIT  2
#define KHALF   (N_NODES / KSPLIT)      // 1024
#define CTILES  (KHALF / KC)            // 4 tiles per CTA
#define LOG2E   1.4426950408889634f
#define ABS2    0x7fffffff7fffffffull
#define PBIAS   8.0f

// Score: 512 CTAs (256 row-blocks x 2 k-halves), 128 thr (4 warps x 2 rows)
#define S_STAGE_FLOATS (KC * OUT_F + KC)      // 8448
#define S_STAGE_BYTES  (S_STAGE_FLOATS * 4)   // 33792
#define S_SMEM_BYTES   (2 * S_STAGE_BYTES)    // 67584

// Agg: 512 CTAs (256 row-blocks x 2 k-halves), 128 thr (4 warps x 2 rows)
#define A_STAGE_BYTES  (KC * OUT_F * 4)       // 32768
#define A_SMEM_BYTES   (2 * A_STAGE_BYTES)    // 65536

__device__ float          g_Wh1[N_NODES * OUT_F];    // raw Wh1
__device__ float          g_Wh2[N_NODES * OUT_F];    // raw Wh2
__device__ float          g_c6L[N_NODES];            // log2e*0.6*dot(a,Wh1[i]) - PBIAS
__device__ float          g_dk6L[N_NODES];           // log2e*0.6*dot(a,Wh2[k])
__device__ unsigned short g_P[N_NODES * N_NODES];    // fp16 p * 2^-PBIAS
__device__ float          g_L[N_NODES];              // atomically accumulated row sums
__device__ float          g_outacc[N_NODES * OUT_F]; // atomically accumulated numerators

// ---------------------------------------------------------------------------
// Kernel 1: projections + constants + zero-init of accumulators.
// 512 CTAs x 128 thr, 4 rows/CTA (one row per warp), W via cp.async.
// ---------------------------------------------------------------------------
__global__ __launch_bounds__(128) void gat_gemm_kernel(
    const float* __restrict__ h, const float* __restrict__ W,
    const float* __restrict__ a)
{
    __shared__ float Ws[2 * IN_F * OUT_F];   // 32 KB
    __shared__ float hs[4][IN_F];            // 2 KB
    const int tid = threadIdx.x, w = tid >> 5, lane = tid & 31;
    const int row0 = blockIdx.x * 4;

    {
        const uint32_t wsb = (uint32_t)__cvta_generic_to_shared(Ws);
        const uint32_t hsb = (uint32_t)__cvta_generic_to_shared(&hs[0][0]);
        const float4* gw = (const float4*)W;
        const float4* gh = (const float4*)(h + (size_t)row0 * IN_F);
#pragma unroll
        for (int i = 0; i < 16; ++i)
            asm volatile("cp.async.cg.shared.global [%0], [%1], 16;"
                         :: "r"(wsb + (uint32_t)((tid + i * 128) * 16)),
                            "l"(gw + tid + i * 128) : "memory");
        asm volatile("cp.async.cg.shared.global [%0], [%1], 16;"
                     :: "r"(hsb + (uint32_t)(tid * 16)), "l"(gh + tid) : "memory");
        asm volatile("cp.async.commit_group;" ::: "memory");
        asm volatile("cp.async.wait_group 0;" ::: "memory");
    }
    __syncthreads();

    const int row = row0 + w;
    float wh1 = 0.f, wh2 = 0.f;
#pragma unroll 8
    for (int j = 0; j < IN_F; ++j) {
        const float hv = hs[w][j];
        wh1 = fmaf(hv, Ws[j * OUT_F + lane], wh1);
        wh2 = fmaf(hv, Ws[(IN_F + j) * OUT_F + lane], wh2);
    }
    g_Wh1[row * OUT_F + lane] = wh1;
    g_Wh2[row * OUT_F + lane] = wh2;

    const float av = __ldg(a + lane);
    float c = av * wh1, d = av * wh2;
#pragma unroll
    for (int o = 16; o; o >>= 1) {
        c += __shfl_xor_sync(0xffffffffu, c, o);
        d += __shfl_xor_sync(0xffffffffu, d, o);
    }
    if (lane == 0) {
        g_c6L[row]  = (0.6f * LOG2E) * c - PBIAS;
        g_dk6L[row] = (0.6f * LOG2E) * d;
        g_L[row]    = 0.f;
    }
    g_outacc[blockIdx.x * 128 + tid] = 0.f;   // 512*128 == 2048*32 exactly
}

// ---------------------------------------------------------------------------
// Kernel 2: scores -> masked p (fp16, biased) + atomic row sums.
// CTA = (8 rows) x (1024 k).  3 CTAs/SM -> 12 warps/SM.
// ---------------------------------------------------------------------------
extern __shared__ float smem2[];

__device__ __forceinline__ void issue_tile_score(int gt, int slot, uint32_t smem_u, int tid)
{
    const uint32_t w2b = smem_u + slot * S_STAGE_BYTES;
    const uint32_t dkb = w2b + KC * OUT_F * 4;
    const float4* g2 = ((const float4*)g_Wh2) + gt * (KC * 8);
    for (int i = tid; i < KC * 8; i += 128) {
        int kk = i >> 3, f4 = i & 7;
        uint32_t soff = (uint32_t)(((kk << 3) | (f4 ^ (kk & 7))) << 4);
        asm volatile("cp.async.cg.shared.global [%0], [%1], 16;"
                     :: "r"(w2b + soff), "l"(g2 + i) : "memory");
    }
    const float* gd = g_dk6L + gt * KC;
    for (int i = tid; i < KC; i += 128)
        asm volatile("cp.async.ca.shared.global [%0], [%1], 4;"
                     :: "r"(dkb + (uint32_t)(i * 4)), "l"(gd + i) : "memory");
    asm volatile("cp.async.commit_group;" ::: "memory");
}

__global__ __launch_bounds__(128, 3) void gat_score_kernel(
    const int* __restrict__ adj, const float* __restrict__ a)
{
    const int tid = threadIdx.x, w = tid >> 5, lane = tid & 31;
    const uint32_t smem_u = (uint32_t)__cvta_generic_to_shared(smem2);
    const int rb = blockIdx.x >> 1, ks = blockIdx.x & 1;
    const int row0 = rb * 8 + 2 * w, row1 = row0 + 1;
    const int kbase = ks * KHALF;

    unsigned long long wh1p[2][16], a4L[16];
#pragma unroll
    for (int j = 0; j < 16; ++j) {
        float a0 = __ldg(a + 2 * j), a1 = __ldg(a + 2 * j + 1);
        float A0 = (0.4f * LOG2E) * a0, A1 = (0.4f * LOG2E) * a1;
        float x0 = g_Wh1[row0 * OUT_F + 2 * j], x1 = g_Wh1[row0 * OUT_F + 2 * j + 1];
        float y0 = g_Wh1[row1 * OUT_F + 2 * j], y1 = g_Wh1[row1 * OUT_F + 2 * j + 1];
        asm("mov.b64 %0, {%1, %2};" : "=l"(a4L[j])     : "f"(A0), "f"(A1));
        asm("mov.b64 %0, {%1, %2};" : "=l"(wh1p[0][j]) : "f"(x0), "f"(x1));
        asm("mov.b64 %0, {%1, %2};" : "=l"(wh1p[1][j]) : "f"(y0), "f"(y1));
    }
    const float c0 = g_c6L[row0], c1 = g_c6L[row1];
    float lsum0 = 0.f, lsum1 = 0.f;

    const int* adjr0 = adj + (size_t)row0 * N_NODES + kbase;
    const int* adjr1 = adj + (size_t)row1 * N_NODES + kbase;
    unsigned short* p0base = g_P + (size_t)row0 * N_NODES + kbase + lane;
    unsigned short* p1base = g_P + (size_t)row1 * N_NODES + kbase + lane;

    int am0[NSTEP], am1[NSTEP];
#pragma unroll
    for (int s = 0; s < NSTEP; ++s) {
        am0[s] = __ldg(adjr0 + (s << 5) + lane);
        am1[s] = __ldg(adjr1 + (s << 5) + lane);
    }

    issue_tile_score(ks * CTILES, 0, smem_u, tid);

#pragma unroll 1
    for (int t = 0; t < CTILES; ++t) {
        __syncthreads();
        if (t + 1 < CTILES) {
            issue_tile_score(ks * CTILES + t + 1, (t + 1) & 1, smem_u, tid);
            asm volatile("cp.async.wait_group 1;" ::: "memory");
        } else {
            asm volatile("cp.async.wait_group 0;" ::: "memory");
        }
        __syncthreads();

        const uint32_t w2b = smem_u + (t & 1) * S_STAGE_BYTES;
        const float* sdk = smem2 + (t & 1) * S_STAGE_FLOATS + KC * OUT_F;
        const int tn = (t + 1) & (CTILES - 1);
        const int* nadj0 = adjr0 + (tn << 8);
        const int* nadj1 = adjr1 + (tn << 8);

#pragma unroll
        for (int step = 0; step < NSTEP; ++step) {
            const int kk = (step << 5) | lane;
            const int av0 = am0[step], av1 = am1[step];
            am0[step] = __ldg(nadj0 + (step << 5) + lane);
            am1[step] = __ldg(nadj1 + (step << 5) + lane);
            const float dkv = sdk[kk];
            const uint32_t rb2 = w2b + (uint32_t)(kk << 7);
            const int sx = kk & 7;

            unsigned long long s0a = 0ull, s0b = 0ull, s1a = 0ull, s1b = 0ull;
#pragma unroll
            for (int f4 = 0; f4 < 8; ++f4) {
                unsigned long long v0, v1, u;
                asm volatile("ld.shared.v2.b64 {%0, %1}, [%2];"
                             : "=l"(v0), "=l"(v1) : "r"(rb2 + (uint32_t)((f4 ^ sx) << 4)));
                const int j0 = 2 * f4, j1 = 2 * f4 + 1;
                asm("add.rn.f32x2 %0, %1, %2;" : "=l"(u) : "l"(wh1p[0][j0]), "l"(v0));
                u &= ABS2;
                asm("fma.rn.f32x2 %0, %1, %2, %0;" : "+l"(s0a) : "l"(a4L[j0]), "l"(u));
                asm("add.rn.f32x2 %0, %1, %2;" : "=l"(u) : "l"(wh1p[0][j1]), "l"(v1));
                u &= ABS2;
                asm("fma.rn.f32x2 %0, %1, %2, %0;" : "+l"(s0b) : "l"(a4L[j1]), "l"(u));
                asm("add.rn.f32x2 %0, %1, %2;" : "=l"(u) : "l"(wh1p[1][j0]), "l"(v0));
                u &= ABS2;
                asm("fma.rn.f32x2 %0, %1, %2, %0;" : "+l"(s1a) : "l"(a4L[j0]), "l"(u));
                asm("add.rn.f32x2 %0, %1, %2;" : "=l"(u) : "l"(wh1p[1][j1]), "l"(v1));
                u &= ABS2;
                asm("fma.rn.f32x2 %0, %1, %2, %0;" : "+l"(s1b) : "l"(a4L[j1]), "l"(u));
            }

            const int koff = (t << 8) + (step << 5);
            {
                unsigned long long ts; float lo, hi, e, p, pu;
                unsigned short us;
                asm("add.rn.f32x2 %0, %1, %2;" : "=l"(ts) : "l"(s0a), "l"(s0b));
                asm("mov.b64 {%0, %1}, %2;" : "=f"(lo), "=f"(hi) : "l"(ts));
                e = (c0 + dkv) + (lo + hi);
                asm("ex2.approx.f32 %0, %1;" : "=f"(p) : "f"(e));
                p = (av0 > 0) ? p : 0.f;
                asm("cvt.rn.f16.f32 %0, %1;" : "=h"(us) : "f"(p));
                asm("cvt.f32.f16 %0, %1;" : "=f"(pu) : "h"(us));
                lsum0 += pu;
                p0base[koff] = us;
                asm("add.rn.f32x2 %0, %1, %2;" : "=l"(ts) : "l"(s1a), "l"(s1b));
                asm("mov.b64 {%0, %1}, %2;" : "=f"(lo), "=f"(hi) : "l"(ts));
                e = (c1 + dkv) + (lo + hi);
                asm("ex2.approx.f32 %0, %1;" : "=f"(p) : "f"(e));
                p = (av1 > 0) ? p : 0.f;
                asm("cvt.rn.f16.f32 %0, %1;" : "=h"(us) : "f"(p));
                asm("cvt.f32.f16 %0, %1;" : "=f"(pu) : "h"(us));
                lsum1 += pu;
                p1base[koff] = us;
            }
        }
    }

#pragma unroll
    for (int o = 16; o; o >>= 1) {
        lsum0 += __shfl_xor_sync(0xffffffffu, lsum0, o);
        lsum1 += __shfl_xor_sync(0xffffffffu, lsum1, o);
    }
    if (lane == 0) {
        atomicAdd(&g_L[row0], lsum0);
        atomicAdd(&g_L[row1], lsum1);
    }
}

// ---------------------------------------------------------------------------
// Kernel 3: numerator accumulation  g_outacc += P-half @ Wh1-half
// ---------------------------------------------------------------------------
__device__ __forceinline__ void issue_tile_agg(int gt, int slot, uint32_t smem_u, int tid)
{
    const uint32_t w1b = smem_u + slot * A_STAGE_BYTES;
    const float4* g1 = ((const float4*)g_Wh1) + gt * (KC * 8);
    for (int i = tid; i < KC * 8; i += 128) {
        int kk = i >> 3, f4 = i & 7;
        uint32_t soff = (uint32_t)(((kk << 3) | (f4 ^ (kk & 7))) << 4);
        asm volatile("cp.async.cg.shared.global [%0], [%1], 16;"
                     :: "r"(w1b + soff), "l"(g1 + i) : "memory");
    }
    asm volatile("cp.async.commit_group;" ::: "memory");
}

__global__ __launch_bounds__(128, 3) void gat_agg_kernel()
{
    const int tid = threadIdx.x, w = tid >> 5, lane = tid & 31;
    const uint32_t smem_u = (uint32_t)__cvta_generic_to_shared(smem2);
    const int rb = blockIdx.x >> 1, ks = blockIdx.x & 1;
    const int row0 = rb * 8 + 2 * w, row1 = row0 + 1;
    const int kbase = ks * KHALF;

    unsigned long long acc[2][16];
#pragma unroll
    for (int j = 0; j < 16; ++j) { acc[0][j] = 0ull; acc[1][j] = 0ull; }

    const unsigned short* pB0 = g_P + (size_t)row0 * N_NODES + kbase + lane;
    const unsigned short* pB1 = g_P + (size_t)row1 * N_NODES + kbase + lane;

    unsigned pr0[NSTEP], pr1[NSTEP];
#pragma unroll
    for (int s = 0; s < NSTEP; ++s) {
        pr0[s] = __ldg(pB0 + (s << 5));
        pr1[s] = __ldg(pB1 + (s << 5));
    }

    issue_tile_agg(ks * CTILES, 0, smem_u, tid);

#pragma unroll 1
    for (int t = 0; t < CTILES; ++t) {
        __syncthreads();
        if (t + 1 < CTILES) {
            issue_tile_agg(ks * CTILES + t + 1, (t + 1) & 1, smem_u, tid);
            asm volatile("cp.async.wait_group 1;" ::: "memory");
        } else {
            asm volatile("cp.async.wait_group 0;" ::: "memory");
        }
        __syncthreads();

        const uint32_t w1b = smem_u + (t & 1) * A_STAGE_BYTES;
        const int noff = ((t + 1) & (CTILES - 1)) << 8;

#pragma unroll
        for (int step = 0; step < NSTEP; ++step) {
            const int kk = (step << 5) | lane;
            float pf0, pf1;
            asm("cvt.f32.f16 %0, %1;" : "=f"(pf0) : "h"((unsigned short)pr0[step]));
            asm("cvt.f32.f16 %0, %1;" : "=f"(pf1) : "h"((unsigned short)pr1[step]));
            pr0[step] = __ldg(pB0 + noff + (step << 5));
            pr1[step] = __ldg(pB1 + noff + (step << 5));
            unsigned long long p20, p21;
            asm("mov.b64 %0, {%1, %1};" : "=l"(p20) : "f"(pf0));
            asm("mov.b64 %0, {%1, %1};" : "=l"(p21) : "f"(pf1));
            const uint32_t rb1 = w1b + (uint32_t)(kk << 7);
            const int sx = kk & 7;
#pragma unroll
            for (int f4 = 0; f4 < 8; ++f4) {
                unsigned long long v0, v1;
                asm volatile("ld.shared.v2.b64 {%0, %1}, [%2];"
                             : "=l"(v0), "=l"(v1) : "r"(rb1 + (uint32_t)((f4 ^ sx) << 4)));
                asm("fma.rn.f32x2 %0, %1, %2, %0;" : "+l"(acc[0][2*f4])   : "l"(p20), "l"(v0));
                asm("fma.rn.f32x2 %0, %1, %2, %0;" : "+l"(acc[0][2*f4+1]) : "l"(p20), "l"(v1));
                asm("fma.rn.f32x2 %0, %1, %2, %0;" : "+l"(acc[1][2*f4])   : "l"(p21), "l"(v0));
                asm("fma.rn.f32x2 %0, %1, %2, %0;" : "+l"(acc[1][2*f4+1]) : "l"(p21), "l"(v1));
            }
        }
    }

    __syncthreads();
    float* red = smem2 + w * (32 * 33);
#pragma unroll 1
    for (int r = 0; r < 2; ++r) {
#pragma unroll
        for (int j = 0; j < 16; ++j) {
            float lo, hi;
            asm("mov.b64 {%0, %1}, %2;" : "=f"(lo), "=f"(hi) : "l"(acc[r][j]));
            red[lane * 33 + 2 * j]     = lo;
            red[lane * 33 + 2 * j + 1] = hi;
        }
        __syncwarp();
        float tot = 0.f;
#pragma unroll 8
        for (int jj = 0; jj < 32; ++jj) tot += red[jj * 33 + lane];
        const int row = r ? row1 : row0;
        atomicAdd(&g_outacc[row * OUT_F + lane], tot);
        __syncwarp();
    }
}

// ---------------------------------------------------------------------------
// Kernel 4: out = ELU(outacc / L)
// ---------------------------------------------------------------------------
__global__ __launch_bounds__(512) void gat_final_kernel(float* __restrict__ out)
{
    const int idx = blockIdx.x * 512 + threadIdx.x;
    const float v = g_outacc[idx] / g_L[idx >> 5];
    out[idx] = v > 0.f ? v : expm1f(v);
}

// ---------------------------------------------------------------------------
extern "C" void kernel_launch(void* const* d_in, const int* in_sizes, int n_in,
                              void* d_out, int out_size)
{
    const float* h   = (const float*)d_in[0];
    const int*   adj = (const int*)  d_in[1];
    const float* W   = (const float*)d_in[2];
    const float* a   = (const float*)d_in[3];
    float*       out = (float*)d_out;

    gat_gemm_kernel<<<N_NODES / 4, 128>>>(h, W, a);

    cudaFuncSetAttribute(gat_score_kernel,
                         cudaFuncAttributeMaxDynamicSharedMemorySize, S_SMEM_BYTES);
    gat_score_kernel<<<512, 128, S_SMEM_BYTES>>>(adj, a);

    cudaFuncSetAttribute(gat_agg_kernel,
                         cudaFuncAttributeMaxDynamicSharedMemorySize, A_SMEM_BYTES);
    gat_agg_kernel<<<512, 128, A_SMEM_BYTES>>>();

    gat_final_kernel<<<(N_NODES * OUT_F) / 512, 512>>>(out);
}

// round 9
// speedup vs baseline: 1.4352x; 1.3356x over previous
#include <cuda_runtime.h>
#include <math.h>
#include <stdint.h>

#define N_NODES 2048
#define IN_F    128
#define OUT_F   32
#define KC      128
#define NTILES  (N_NODES / KC)          // 16
#define NSTEP   (KC / 32)               // 4
#define WARPS   7
#define THREADS (WARPS * 32)            // 224
#define GRID    148                     // 148*14 = 2072 >= 2048 rows, 1 CTA/SM
#define STAGE_FLOATS (2 * KC * OUT_F + KC)   // 8320
#define STAGE_BYTES  (STAGE_FLOATS * 4)      // 33280
#define SMEM_BYTES   (2 * STAGE_BYTES)       // 66560
#define LOG2E 1.4426950408889634f
#define ABS2  0x7fffffff7fffffffull

__device__ float g_Wh1[N_NODES * OUT_F];   // raw Wh1
__device__ float g_Wh2[N_NODES * OUT_F];   // raw Wh2
__device__ float g_c6L[N_NODES];           // log2e*0.6*dot(a,Wh1[i])
__device__ float g_dk6L[N_NODES];          // log2e*0.6*dot(a,Wh2[k])

// ---------------------------------------------------------------------------
// Kernel 1: projections + per-row constants. 512 CTAs x 128 thr, warp-per-row.
// ---------------------------------------------------------------------------
__global__ __launch_bounds__(128) void gat_gemm_kernel(
    const float* __restrict__ h, const float* __restrict__ W,
    const float* __restrict__ a)
{
    __shared__ float Ws[2 * IN_F * OUT_F];   // 32 KB
    __shared__ float hs[4][IN_F];            // 2 KB
    const int tid = threadIdx.x, w = tid >> 5, lane = tid & 31;
    const int row0 = blockIdx.x * 4;

    {
        const uint32_t wsb = (uint32_t)__cvta_generic_to_shared(Ws);
        const uint32_t hsb = (uint32_t)__cvta_generic_to_shared(&hs[0][0]);
        const float4* gw = (const float4*)W;
        const float4* gh = (const float4*)(h + (size_t)row0 * IN_F);
#pragma unroll
        for (int i = 0; i < 16; ++i)
            asm volatile("cp.async.cg.shared.global [%0], [%1], 16;"
                         :: "r"(wsb + (uint32_t)((tid + i * 128) * 16)),
                            "l"(gw + tid + i * 128) : "memory");
        asm volatile("cp.async.cg.shared.global [%0], [%1], 16;"
                     :: "r"(hsb + (uint32_t)(tid * 16)), "l"(gh + tid) : "memory");
        asm volatile("cp.async.commit_group;" ::: "memory");
        asm volatile("cp.async.wait_group 0;" ::: "memory");
    }
    __syncthreads();

    const int row = row0 + w;
    float wh1 = 0.f, wh2 = 0.f;
#pragma unroll 8
    for (int j = 0; j < IN_F; ++j) {
        const float hv = hs[w][j];
        wh1 = fmaf(hv, Ws[j * OUT_F + lane], wh1);
        wh2 = fmaf(hv, Ws[(IN_F + j) * OUT_F + lane], wh2);
    }
    g_Wh1[row * OUT_F + lane] = wh1;
    g_Wh2[row * OUT_F + lane] = wh2;

    const float av = __ldg(a + lane);
    float c = av * wh1, d = av * wh2;
#pragma unroll
    for (int o = 16; o; o >>= 1) {
        c += __shfl_xor_sync(0xffffffffu, c, o);
        d += __shfl_xor_sync(0xffffffffu, d, o);
    }
    if (lane == 0) {
        g_c6L[row]  = (0.6f * LOG2E) * c;
        g_dk6L[row] = (0.6f * LOG2E) * d;
    }
}

// ---------------------------------------------------------------------------
// Kernel 2: fused score + masked softmax (no max-shift) + aggregation + ELU.
// 2 rows/lane, KC=128 double-buffered, step loop unrolled (4), tile loop rolled.
// ---------------------------------------------------------------------------
extern __shared__ float smem2[];

__device__ __forceinline__ void issue_tile(int t, uint32_t smem_u, int tid)
{
    const uint32_t w2b = smem_u + (t & 1) * STAGE_BYTES;
    const uint32_t w1b = w2b + KC * OUT_F * 4;
    const uint32_t dkb = w2b + 2 * KC * OUT_F * 4;
    const float4* g2 = ((const float4*)g_Wh2) + t * (KC * 8);
    const float4* g1 = ((const float4*)g_Wh1) + t * (KC * 8);
    for (int i = tid; i < KC * 8; i += THREADS) {
        int kk = i >> 3, f4 = i & 7;
        uint32_t soff = (uint32_t)(((kk << 3) | (f4 ^ (kk & 7))) << 4);
        asm volatile("cp.async.cg.shared.global [%0], [%1], 16;"
                     :: "r"(w2b + soff), "l"(g2 + i) : "memory");
        asm volatile("cp.async.cg.shared.global [%0], [%1], 16;"
                     :: "r"(w1b + soff), "l"(g1 + i) : "memory");
    }
    const float* gd = g_dk6L + t * KC;
    for (int i = tid; i < KC; i += THREADS)
        asm volatile("cp.async.ca.shared.global [%0], [%1], 4;"
                     :: "r"(dkb + (uint32_t)(i * 4)), "l"(gd + i) : "memory");
    asm volatile("cp.async.commit_group;" ::: "memory");
}

__global__ __launch_bounds__(THREADS, 1) void gat_attn_kernel(
    const int* __restrict__ adj, const float* __restrict__ a,
    float* __restrict__ out)
{
    const int tid = threadIdx.x, w = tid >> 5, lane = tid & 31;
    const uint32_t smem_u = (uint32_t)__cvta_generic_to_shared(smem2);
    int row0 = blockIdx.x * 14 + 2 * w;
    int row1 = row0 + 1;
    if (row1 >= N_NODES) { row0 = N_NODES - 2; row1 = N_NODES - 1; }

    unsigned long long wh1p[2][16], acc[2][16], a4L[16];
#pragma unroll
    for (int j = 0; j < 16; ++j) {
        float a0 = __ldg(a + 2 * j), a1 = __ldg(a + 2 * j + 1);
        float A0 = (0.4f * LOG2E) * a0, A1 = (0.4f * LOG2E) * a1;
        float x0 = g_Wh1[row0 * OUT_F + 2 * j], x1 = g_Wh1[row0 * OUT_F + 2 * j + 1];
        float y0 = g_Wh1[row1 * OUT_F + 2 * j], y1 = g_Wh1[row1 * OUT_F + 2 * j + 1];
        asm("mov.b64 %0, {%1, %2};" : "=l"(a4L[j])     : "f"(A0), "f"(A1));
        asm("mov.b64 %0, {%1, %2};" : "=l"(wh1p[0][j]) : "f"(x0), "f"(x1));
        asm("mov.b64 %0, {%1, %2};" : "=l"(wh1p[1][j]) : "f"(y0), "f"(y1));
        acc[0][j] = 0ull; acc[1][j] = 0ull;
    }
    const float c0 = g_c6L[row0], c1 = g_c6L[row1];
    float lsum0 = 0.f, lsum1 = 0.f;

    const int* adjr0 = adj + (size_t)row0 * N_NODES;
    const int* adjr1 = adj + (size_t)row1 * N_NODES;

    // Adjacency for the CURRENT tile in registers; prefetch one tile ahead.
    int am0[NSTEP], am1[NSTEP];
#pragma unroll
    for (int s = 0; s < NSTEP; ++s) {
        am0[s] = __ldg(adjr0 + (s << 5) + lane);
        am1[s] = __ldg(adjr1 + (s << 5) + lane);
    }

    issue_tile(0, smem_u, tid);

#pragma unroll 1
    for (int t = 0; t < NTILES; ++t) {
        __syncthreads();
        if (t + 1 < NTILES) {
            issue_tile(t + 1, smem_u, tid);
            asm volatile("cp.async.wait_group 1;" ::: "memory");
        } else {
            asm volatile("cp.async.wait_group 0;" ::: "memory");
        }
        __syncthreads();

        const uint32_t w2b = smem_u + (t & 1) * STAGE_BYTES;
        const uint32_t w1b = w2b + KC * OUT_F * 4;
        const float* sdk = smem2 + (t & 1) * STAGE_FLOATS + 2 * KC * OUT_F;
        const int tn = (t + 1) & (NTILES - 1);
        const int* nadj0 = adjr0 + (tn << 7);
        const int* nadj1 = adjr1 + (tn << 7);

#pragma unroll
        for (int step = 0; step < NSTEP; ++step) {
            const int kk = (step << 5) | lane;
            const int av0 = am0[step], av1 = am1[step];
            am0[step] = __ldg(nadj0 + (step << 5) + lane);
            am1[step] = __ldg(nadj1 + (step << 5) + lane);
            const float dkv = sdk[kk];
            const uint32_t rb2 = w2b + (uint32_t)(kk << 7);
            const uint32_t rb1 = w1b + (uint32_t)(kk << 7);
            const int sx = kk & 7;

            unsigned long long s0a = 0ull, s0b = 0ull, s1a = 0ull, s1b = 0ull;
#pragma unroll
            for (int f4 = 0; f4 < 8; ++f4) {
                unsigned long long v0, v1, u;
                asm volatile("ld.shared.v2.b64 {%0, %1}, [%2];"
                             : "=l"(v0), "=l"(v1) : "r"(rb2 + (uint32_t)((f4 ^ sx) << 4)));
                const int j0 = 2 * f4, j1 = 2 * f4 + 1;
                asm("add.rn.f32x2 %0, %1, %2;" : "=l"(u) : "l"(wh1p[0][j0]), "l"(v0));
                u &= ABS2;
                asm("fma.rn.f32x2 %0, %1, %2, %0;" : "+l"(s0a) : "l"(a4L[j0]), "l"(u));
                asm("add.rn.f32x2 %0, %1, %2;" : "=l"(u) : "l"(wh1p[0][j1]), "l"(v1));
                u &= ABS2;
                asm("fma.rn.f32x2 %0, %1, %2, %0;" : "+l"(s0b) : "l"(a4L[j1]), "l"(u));
                asm("add.rn.f32x2 %0, %1, %2;" : "=l"(u) : "l"(wh1p[1][j0]), "l"(v0));
                u &= ABS2;
                asm("fma.rn.f32x2 %0, %1, %2, %0;" : "+l"(s1a) : "l"(a4L[j0]), "l"(u));
                asm("add.rn.f32x2 %0, %1, %2;" : "=l"(u) : "l"(wh1p[1][j1]), "l"(v1));
                u &= ABS2;
                asm("fma.rn.f32x2 %0, %1, %2, %0;" : "+l"(s1b) : "l"(a4L[j1]), "l"(u));
            }

            float p0, p1;
            {
                unsigned long long ts; float lo, hi, e;
                asm("add.rn.f32x2 %0, %1, %2;" : "=l"(ts) : "l"(s0a), "l"(s0b));
                asm("mov.b64 {%0, %1}, %2;" : "=f"(lo), "=f"(hi) : "l"(ts));
                e = (c0 + dkv) + (lo + hi);
                asm("ex2.approx.f32 %0, %1;" : "=f"(p0) : "f"(e));
                p0 = (av0 > 0) ? p0 : 0.f;
                asm("add.rn.f32x2 %0, %1, %2;" : "=l"(ts) : "l"(s1a), "l"(s1b));
                asm("mov.b64 {%0, %1}, %2;" : "=f"(lo), "=f"(hi) : "l"(ts));
                e = (c1 + dkv) + (lo + hi);
                asm("ex2.approx.f32 %0, %1;" : "=f"(p1) : "f"(e));
                p1 = (av1 > 0) ? p1 : 0.f;
            }
            lsum0 += p0; lsum1 += p1;
            unsigned long long p20, p21;
            asm("mov.b64 %0, {%1, %1};" : "=l"(p20) : "f"(p0));
            asm("mov.b64 %0, {%1, %1};" : "=l"(p21) : "f"(p1));

#pragma unroll
            for (int f4 = 0; f4 < 8; ++f4) {
                unsigned long long v0, v1;
                asm volatile("ld.shared.v2.b64 {%0, %1}, [%2];"
                             : "=l"(v0), "=l"(v1) : "r"(rb1 + (uint32_t)((f4 ^ sx) << 4)));
                asm("fma.rn.f32x2 %0, %1, %2, %0;" : "+l"(acc[0][2*f4])   : "l"(p20), "l"(v0));
                asm("fma.rn.f32x2 %0, %1, %2, %0;" : "+l"(acc[0][2*f4+1]) : "l"(p20), "l"(v1));
                asm("fma.rn.f32x2 %0, %1, %2, %0;" : "+l"(acc[1][2*f4])   : "l"(p21), "l"(v0));
                asm("fma.rn.f32x2 %0, %1, %2, %0;" : "+l"(acc[1][2*f4+1]) : "l"(p21), "l"(v1));
            }
        }
    }

    // ---- Epilogue: cross-lane reduce, divide, ELU ----
    float L0 = lsum0, L1 = lsum1;
#pragma unroll
    for (int o = 16; o; o >>= 1) {
        L0 += __shfl_xor_sync(0xffffffffu, L0, o);
        L1 += __shfl_xor_sync(0xffffffffu, L1, o);
    }
    __syncthreads();                       // tile stages no longer needed
    float* red = smem2 + w * (32 * 33);
#pragma unroll 1
    for (int r = 0; r < 2; ++r) {
#pragma unroll
        for (int j = 0; j < 16; ++j) {
            float lo, hi;
            asm("mov.b64 {%0, %1}, %2;" : "=f"(lo), "=f"(hi) : "l"(acc[r][j]));
            red[lane * 33 + 2 * j]     = lo;
            red[lane * 33 + 2 * j + 1] = hi;
        }
        __syncwarp();
        float tot = 0.f;
#pragma unroll 8
        for (int jj = 0; jj < 32; ++jj) tot += red[jj * 33 + lane];
        const float L = r ? L1 : L0;
        const int row = r ? row1 : row0;
        const float hv = tot / L;
        out[row * OUT_F + lane] = hv > 0.f ? hv : expm1f(hv);
        __syncwarp();
    }
}

// ---------------------------------------------------------------------------
extern "C" void kernel_launch(void* const* d_in, const int* in_sizes, int n_in,
                              void* d_out, int out_size)
{
    const float* h   = (const float*)d_in[0];
    const int*   adj = (const int*)  d_in[1];
    const float* W   = (const float*)d_in[2];
    const float* a   = (const float*)d_in[3];
    float*       out = (float*)d_out;

    gat_gemm_kernel<<<N_NODES / 4, 128>>>(h, W, a);

    cudaFuncSetAttribute(gat_attn_kernel,
                         cudaFuncAttributeMaxDynamicSharedMemorySize, SMEM_BYTES);
    gat_attn_kernel<<<GRID, THREADS, SMEM_BYTES>>>(adj, a, out);
}